// round 17
// baseline (speedup 1.0000x reference)
#include <cuda_runtime.h>
#include <cuda_bf16.h>
#include <cuda_fp16.h>
#include <math.h>

#define Bsz 2
#define Ssz 2048
#define HIDs 2048
#define Hh 16
#define KVh 8
#define Dh 128
#define KP 2048              // single-f16 GEMM: K' = K = 2048
#define NT 32                // KP / 64 k-chunks
#define STG_A (128 * 72 * 2)            // 18432 B per A tile (stride 144B)
#define STG_BYTES (2 * STG_A)           // 36864
#define GEMM_SMEM (3 * STG_BYTES)       // 3-stage = 110592

// flash smem: per stage K[64][136] f16 + V[64 n][128 d + pad] f16 (272B rows)
#define FKT 17408
#define FLSTG (2 * FKT)                 // 34816
#define FL_SMEM (2 * FLSTG)             // 69632

// ---------------- scratch (static device arrays: no allocs allowed) ----------
__device__ __align__(16) __half g_qkvh[(size_t)4096 * 4096];  // fused QKV f16 [M, 4096]

__device__ __align__(16) __half g_xp[(size_t)4096 * KP];
__device__ __align__(16) __half g_ap[(size_t)4096 * KP];   // att f16 (flash writes)
__device__ __align__(16) __half g_wqkvt[(size_t)4096 * KP];
__device__ __align__(16) __half g_wot[(size_t)2048 * KP];

// head-major f16 for flash Q/K
__device__ __align__(16) __half g_qh[(size_t)Bsz * Hh * Ssz * Dh];
__device__ __align__(16) __half g_kh[(size_t)Bsz * KVh * Ssz * Dh];

// ====================== PTX helpers =========================================
__device__ __forceinline__ unsigned smem_u32(const void* p) {
    unsigned a;
    asm("{ .reg .u64 t; cvta.to.shared.u64 t, %1; cvt.u32.u64 %0, t; }"
        : "=r"(a) : "l"(p));
    return a;
}
#define CP16(dst, src) \
    asm volatile("cp.async.cg.shared.global [%0], [%1], 16;" :: "r"(dst), "l"(src))
#define CP_COMMIT() asm volatile("cp.async.commit_group;")

__device__ __forceinline__ void ldsm4(unsigned& r0, unsigned& r1,
                                      unsigned& r2, unsigned& r3, unsigned a) {
    asm volatile("ldmatrix.sync.aligned.m8n8.x4.shared.b16 {%0,%1,%2,%3}, [%4];"
                 : "=r"(r0), "=r"(r1), "=r"(r2), "=r"(r3) : "r"(a));
}
__device__ __forceinline__ void ldsm4t(unsigned& r0, unsigned& r1,
                                       unsigned& r2, unsigned& r3, unsigned a) {
    asm volatile("ldmatrix.sync.aligned.m8n8.x4.trans.shared.b16 {%0,%1,%2,%3}, [%4];"
                 : "=r"(r0), "=r"(r1), "=r"(r2), "=r"(r3) : "r"(a));
}
// f16 mma
__device__ __forceinline__ void mma16816h(float* d, const unsigned* a,
                                          unsigned b0, unsigned b1) {
    asm volatile(
        "mma.sync.aligned.m16n8k16.row.col.f32.f16.f16.f32 "
        "{%0,%1,%2,%3}, {%4,%5,%6,%7}, {%8,%9}, {%0,%1,%2,%3};"
        : "+f"(d[0]), "+f"(d[1]), "+f"(d[2]), "+f"(d[3])
        : "r"(a[0]), "r"(a[1]), "r"(a[2]), "r"(a[3]), "r"(b0), "r"(b1));
}
__device__ __forceinline__ unsigned pack2h(float lo, float hi) {
    unsigned d;
    asm("cvt.rn.f16x2.f32 %0, %1, %2;" : "=r"(d) : "f"(hi), "f"(lo));
    return d;
}
__device__ __forceinline__ float ex2(float x) {
    float r;
    asm("ex2.approx.f32 %0, %1;" : "=f"(r) : "f"(x));
    return r;
}

// ====================== conversion kernels ==================================
// A' = f16 copy of src [M, 2048] fp32 row-major (single term)
__global__ __launch_bounds__(256) void conv_a(
    const float* __restrict__ src, __half* __restrict__ dst)
{
    size_t i = (size_t)blockIdx.x * 256 + threadIdx.x;   // over M*512 float4
    float4 v = ((const float4*)src)[i];
    __half2* d = (__half2*)dst + i * 2;
    d[0] = __floats2half2_rn(v.x, v.y);
    d[1] = __floats2half2_rn(v.z, v.w);
}

// B' = W^T f16 single [N, 2048].  W is [2048, N] fp32.
__global__ __launch_bounds__(256) void conv_w(
    const float* __restrict__ W, __half* __restrict__ Bt, int N)
{
    __shared__ float ts[32][33];
    int n0 = blockIdx.x * 32, k0 = blockIdx.y * 32;
    int tx = threadIdx.x & 31, ty = threadIdx.x >> 5;
    #pragma unroll
    for (int r = 0; r < 4; ++r)
        ts[ty + r * 8][tx] = W[(size_t)(k0 + ty + r * 8) * N + n0 + tx];
    __syncthreads();
    #pragma unroll
    for (int r = 0; r < 4; ++r) {
        int n = n0 + ty + r * 8, k = k0 + tx;
        Bt[(size_t)n * KP + k] = __float2half(ts[tx][ty + r * 8]);
    }
}

// fused RMSNorm + RoPE for Q AND K in one launch, reading f16 qkv buffer.
// blocks [0, 8192): Q (16 heads); blocks [8192, 12288): K (8 heads).
__global__ __launch_bounds__(256) void norm_rope_split(
    const __half* __restrict__ qkv,
    const float* __restrict__ qw, const float* __restrict__ kw,
    const float* __restrict__ cs, const float* __restrict__ sn,
    __half* __restrict__ dq, __half* __restrict__ dk, float qscale)
{
    const bool isQ = blockIdx.x < 8192;
    const int blk = isQ ? blockIdx.x : blockIdx.x - 8192;
    const int nh = isQ ? Hh : KVh;
    const int baseCol = isQ ? 0 : 2048;
    const float* w = isQ ? qw : kw;
    __half* dh = isQ ? dq : dk;
    const float scale = isQ ? qscale : 1.0f;

    const int warp = blk * 8 + (threadIdx.x >> 5);
    const int lane = threadIdx.x & 31;
    const int tok = warp / nh;          // b*S + s
    const int head = warp % nh;
    const int s = tok % Ssz;
    const int b = tok / Ssz;

    const __half* row = qkv + (size_t)tok * 4096 + baseCol + head * Dh;
    float v0 = __half2float(row[lane]);
    float v1 = __half2float(row[lane + 32]);
    float v2 = __half2float(row[lane + 64]);
    float v3 = __half2float(row[lane + 96]);

    float ss = v0 * v0 + v1 * v1 + v2 * v2 + v3 * v3;
    #pragma unroll
    for (int o = 16; o; o >>= 1) ss += __shfl_xor_sync(0xffffffffu, ss, o);
    float r = rsqrtf(ss * (1.0f / 128.0f) + 1e-6f);

    v0 = v0 * r * w[lane];
    v1 = v1 * r * w[lane + 32];
    v2 = v2 * r * w[lane + 64];
    v3 = v3 * r * w[lane + 96];

    const float* cr = cs + (size_t)s * Dh;
    const float* sr = sn + (size_t)s * Dh;
    float o0 = (v0 * cr[lane]      - v2 * sr[lane])      * scale;
    float o1 = (v1 * cr[lane + 32] - v3 * sr[lane + 32]) * scale;
    float o2 = (v2 * cr[lane + 64] + v0 * sr[lane + 64]) * scale;
    float o3 = (v3 * cr[lane + 96] + v1 * sr[lane + 96]) * scale;

    size_t o = (((size_t)b * nh + head) * Ssz + s) * 128;
    dh[o + lane]      = __float2half(o0);
    dh[o + lane + 32] = __float2half(o1);
    dh[o + lane + 64] = __float2half(o2);
    dh[o + lane + 96] = __float2half(o3);
}

// ====================== f16 GEMM (3-stage, 1 barrier/chunk) =================
// C fp32 or Ch f16 (Ch non-null selects f16 output).
__global__ __launch_bounds__(256, 2) void gemm_mma(
    const __half* __restrict__ A, const __half* __restrict__ Bm,
    float* __restrict__ C, __half* __restrict__ Ch, int N)
{
    extern __shared__ __align__(16) char smem[];
    const unsigned sb = smem_u32(smem);
    const int tid = threadIdx.x;
    const int lane = tid & 31;
    const int wid = tid >> 5;
    const int wr = wid >> 1;
    const int wc = wid & 1;
    const int bm = blockIdx.y << 7, bn = blockIdx.x << 7;

    const int lrow = tid >> 3, lcol = tid & 7;
    const __half* Ag = A + (size_t)(bm + lrow) * KP + lcol * 8;
    const __half* Bg = Bm + (size_t)(bn + lrow) * KP + lcol * 8;
    const unsigned sOff = lrow * 144 + lcol * 16;

    float acc[2][8][4];
    #pragma unroll
    for (int i = 0; i < 2; ++i)
        #pragma unroll
        for (int j = 0; j < 8; ++j)
            #pragma unroll
            for (int e = 0; e < 4; ++e) acc[i][j][e] = 0.0f;

    const unsigned aBase0 = sb + (32 * wr + (lane & 15)) * 144 + (lane >> 4) * 16;
    const unsigned bBase0 = sb + STG_A + (64 * wc + (lane & 15)) * 144 + (lane >> 4) * 16;

    #pragma unroll
    for (int c = 0; c < 2; ++c) {
        const unsigned st = c * STG_BYTES;
        const unsigned as = sb + st + sOff, bs = sb + st + STG_A + sOff;
        const __half* ag = Ag + (size_t)c * 64;
        const __half* bg = Bg + (size_t)c * 64;
        #pragma unroll
        for (int i = 0; i < 4; ++i) {
            CP16(as + i * 32 * 144, ag + (size_t)(32 * i) * KP);
            CP16(bs + i * 32 * 144, bg + (size_t)(32 * i) * KP);
        }
        CP_COMMIT();
    }

    int stage = 0, nstage = 2;
    for (int c = 0; c < NT; ++c) {
        if (c + 1 < NT) asm volatile("cp.async.wait_group 1;" ::: "memory");
        else            asm volatile("cp.async.wait_group 0;" ::: "memory");
        __syncthreads();

        if (c + 2 < NT) {
            const unsigned st = nstage * STG_BYTES;
            const unsigned as = sb + st + sOff, bs = sb + st + STG_A + sOff;
            const __half* ag = Ag + (size_t)(c + 2) * 64;
            const __half* bg = Bg + (size_t)(c + 2) * 64;
            #pragma unroll
            for (int i = 0; i < 4; ++i) {
                CP16(as + i * 32 * 144, ag + (size_t)(32 * i) * KP);
                CP16(bs + i * 32 * 144, bg + (size_t)(32 * i) * KP);
            }
            CP_COMMIT();
            nstage = (nstage == 2) ? 0 : nstage + 1;
        }

        const unsigned st = stage * STG_BYTES;
        stage = (stage == 2) ? 0 : stage + 1;
        const unsigned aB = aBase0 + st, bB = bBase0 + st;
        #pragma unroll
        for (int ks = 0; ks < 4; ++ks) {
            unsigned a[2][4];
            ldsm4(a[0][0], a[0][1], a[0][2], a[0][3], aB + ks * 32);
            ldsm4(a[1][0], a[1][1], a[1][2], a[1][3], aB + 16 * 144 + ks * 32);
            unsigned b[8][2];
            #pragma unroll
            for (int nt = 0; nt < 4; ++nt) {
                unsigned r0, r1, r2, r3;
                ldsm4(r0, r1, r2, r3, bB + nt * 16 * 144 + ks * 32);
                b[nt * 2][0] = r0; b[nt * 2][1] = r2;
                b[nt * 2 + 1][0] = r1; b[nt * 2 + 1][1] = r3;
            }
            #pragma unroll
            for (int mt = 0; mt < 2; ++mt)
                #pragma unroll
                for (int nt = 0; nt < 8; ++nt)
                    mma16816h(acc[mt][nt], a[mt], b[nt][0], b[nt][1]);
        }
    }

    if (Ch) {
        #pragma unroll
        for (int mt = 0; mt < 2; ++mt) {
            const int r0 = bm + 32 * wr + 16 * mt + (lane >> 2);
            #pragma unroll
            for (int nt = 0; nt < 8; ++nt) {
                const int col = bn + 64 * wc + 8 * nt + (lane & 3) * 2;
                *(__half2*)&Ch[(size_t)r0 * N + col] =
                    __floats2half2_rn(acc[mt][nt][0], acc[mt][nt][1]);
                *(__half2*)&Ch[(size_t)(r0 + 8) * N + col] =
                    __floats2half2_rn(acc[mt][nt][2], acc[mt][nt][3]);
            }
        }
    } else {
        #pragma unroll
        for (int mt = 0; mt < 2; ++mt) {
            const int r0 = bm + 32 * wr + 16 * mt + (lane >> 2);
            #pragma unroll
            for (int nt = 0; nt < 8; ++nt) {
                const int col = bn + 64 * wc + 8 * nt + (lane & 3) * 2;
                float2 v0 = make_float2(acc[mt][nt][0], acc[mt][nt][1]);
                float2 v1 = make_float2(acc[mt][nt][2], acc[mt][nt][3]);
                *(float2*)&C[(size_t)r0 * N + col]       = v0;
                *(float2*)&C[(size_t)(r0 + 8) * N + col] = v1;
            }
        }
    }
}

// ====================== f16 flash attention (2 CTAs/SM) =====================
// Per stage: K[64 n][128 d + pad] + V[64 n][128 d + pad], both 272B rows.
// QK computed in two n-halves with immediate f16 packing of P (peak regs <=128).
__device__ __forceinline__ void load_kv_tile(
    unsigned sbase, int tid,
    const __half* khp, const __half* vhp, int nBase)
{
    const int r = tid >> 2, c0 = (tid & 3) * 4;
    const char* gk = (const char*)(khp + (size_t)(nBase + r) * 128) + c0 * 16;
    const unsigned dk = sbase + r * 272 + c0 * 16;
    #pragma unroll
    for (int i = 0; i < 4; ++i) CP16(dk + i * 16, gk + i * 16);
    const char* gv = (const char*)(vhp + (size_t)(nBase + r) * 4096) + c0 * 16;
    const unsigned dv = sbase + FKT + r * 272 + c0 * 16;
    #pragma unroll
    for (int i = 0; i < 4; ++i) CP16(dv + i * 16, gv + i * 16);
}

__global__ __launch_bounds__(256, 2) void flash_mma(
    const __half* __restrict__ qh, const __half* __restrict__ kh,
    const __half* __restrict__ qkvh,
    __half* __restrict__ outp)           // f16 [M, 2048]
{
    extern __shared__ __align__(16) char smem[];
    const unsigned sb = smem_u32(smem);
    const int tid = threadIdx.x, lane = tid & 31, w = tid >> 5;
    const int qi = 15 - blockIdx.x;
    const int h = blockIdx.y, b = blockIdx.z;
    const int kvh = h >> 1;
    const int mBase = qi << 7;
    const int ntiles = 2 * qi + 2;

    const __half* qhp = qh + (((size_t)b * Hh + h) * Ssz + mBase) * Dh;
    const __half* khp = kh + ((size_t)b * KVh + kvh) * Ssz * Dh;
    const __half* vhp = qkvh + (size_t)b * Ssz * 4096 + 3072 + kvh * Dh;

    // prologue: stage Q at sb, extract, then KV tile0
    {
        const int r = tid >> 1, cb = (tid & 1) * 8;
        const unsigned dq = sb + r * 272 + cb * 16;
        const char* gq = (const char*)(qhp + (size_t)r * Dh) + cb * 16;
        #pragma unroll
        for (int i = 0; i < 8; ++i) CP16(dq + i * 16, gq + i * 16);
    }
    CP_COMMIT();
    asm volatile("cp.async.wait_group 0;" ::: "memory");
    __syncthreads();

    unsigned qhf[8][4];
    {
        const unsigned qB = sb + (16 * w + (lane & 15)) * 272 + (lane >> 4) * 16;
        #pragma unroll
        for (int kt = 0; kt < 8; ++kt)
            ldsm4(qhf[kt][0], qhf[kt][1], qhf[kt][2], qhf[kt][3], qB + kt * 32);
    }
    __syncthreads();        // Q fully extracted before overwriting with tile0

    load_kv_tile(sb, tid, khp, vhp, 0);
    CP_COMMIT();

    float o_[16][4];
    #pragma unroll
    for (int n = 0; n < 16; ++n)
        #pragma unroll
        for (int e = 0; e < 4; ++e) o_[n][e] = 0.0f;
    float l_lo = 0.0f, l_hi = 0.0f;
    const int gm_lo = mBase + 16 * w + (lane >> 2);
    const int gm_hi = gm_lo + 8;

    const unsigned vBt0 = ((lane & 7) + ((lane >> 4) << 3)) * 272
                        + ((lane >> 3) & 1) * 16;

    for (int t = 0; t < ntiles; ++t) {
        if (t + 1 < ntiles) {
            load_kv_tile(sb + ((t + 1) & 1) * FLSTG, tid, khp, vhp, (t + 1) * 64);
            CP_COMMIT();
            asm volatile("cp.async.wait_group 1;" ::: "memory");
        } else {
            asm volatile("cp.async.wait_group 0;" ::: "memory");
        }
        __syncthreads();
        const unsigned stb = sb + (t & 1) * FLSTG;
        const unsigned kB = stb + (lane & 15) * 272 + (lane >> 4) * 16;
        const int nBase = t * 64;
        const bool masked = (t >= 2 * qi);

        // ---- QK^T + softmax + pack, in two n-halves (keeps regs <= 128) ----
        unsigned ph[8][2];
        #pragma unroll
        for (int half = 0; half < 2; ++half) {
            float s_[4][4];
            #pragma unroll
            for (int j = 0; j < 4; ++j)
                #pragma unroll
                for (int e = 0; e < 4; ++e) s_[j][e] = 0.0f;

            #pragma unroll
            for (int kt = 0; kt < 8; ++kt) {
                #pragma unroll
                for (int nt = 0; nt < 2; ++nt) {
                    unsigned r0, r1, r2, r3;
                    ldsm4(r0, r1, r2, r3,
                          kB + (half * 2 + nt) * 16 * 272 + kt * 32);
                    mma16816h(s_[nt * 2],     qhf[kt], r0, r2);
                    mma16816h(s_[nt * 2 + 1], qhf[kt], r1, r3);
                }
            }

            if (masked) {
                #pragma unroll
                for (int j = 0; j < 4; ++j) {
                    const int gn0 = nBase + 8 * (half * 4 + j) + (lane & 3) * 2;
                    if (gn0 > gm_lo)     s_[j][0] = -1e30f;
                    if (gn0 + 1 > gm_lo) s_[j][1] = -1e30f;
                    if (gn0 > gm_hi)     s_[j][2] = -1e30f;
                    if (gn0 + 1 > gm_hi) s_[j][3] = -1e30f;
                }
            }
            #pragma unroll
            for (int j = 0; j < 4; ++j) {
                float p0 = ex2(s_[j][0]);
                float p1 = ex2(s_[j][1]);
                float p2 = ex2(s_[j][2]);
                float p3 = ex2(s_[j][3]);
                l_lo += p0 + p1; l_hi += p2 + p3;
                ph[half * 4 + j][0] = pack2h(p0, p1);
                ph[half * 4 + j][1] = pack2h(p2, p3);
            }
        }

        // ---- PV (single term, P packed in registers, V via ldsm.trans) ----
        const unsigned vB = stb + FKT + vBt0;
        #pragma unroll
        for (int kt2 = 0; kt2 < 4; ++kt2) {
            unsigned ahf[4];
            ahf[0] = ph[2 * kt2][0];     ahf[1] = ph[2 * kt2][1];
            ahf[2] = ph[2 * kt2 + 1][0]; ahf[3] = ph[2 * kt2 + 1][1];
            #pragma unroll
            for (int vt = 0; vt < 8; ++vt) {
                unsigned r0, r1, r2, r3;
                ldsm4t(r0, r1, r2, r3, vB + kt2 * 16 * 272 + vt * 32);
                mma16816h(o_[2 * vt],     ahf, r0, r2);
                mma16816h(o_[2 * vt + 1], ahf, r1, r3);
            }
        }
        __syncthreads();
    }

    // ---- epilogue: reduce l across quad, normalize, write f16 ----
    l_lo += __shfl_xor_sync(0xffffffffu, l_lo, 1);
    l_lo += __shfl_xor_sync(0xffffffffu, l_lo, 2);
    l_hi += __shfl_xor_sync(0xffffffffu, l_hi, 1);
    l_hi += __shfl_xor_sync(0xffffffffu, l_hi, 2);
    const float il = 1.0f / l_lo, ih = 1.0f / l_hi;
    __half* arl = outp + (size_t)(b * Ssz + gm_lo) * KP + h * Dh;
    __half* arh = outp + (size_t)(b * Ssz + gm_hi) * KP + h * Dh;
    #pragma unroll
    for (int n = 0; n < 16; ++n) {
        const int col = 8 * n + (lane & 3) * 2;
        *(__half2*)(arl + col) = __floats2half2_rn(o_[n][0] * il, o_[n][1] * il);
        *(__half2*)(arh + col) = __floats2half2_rn(o_[n][2] * ih, o_[n][3] * ih);
    }
}

// ---------------- host launch -------------------------------------------------
extern "C" void kernel_launch(void* const* d_in, const int* in_sizes, int n_in,
                              void* d_out, int out_size)
{
    const float* x   = (const float*)d_in[0];
    const float* Wq  = (const float*)d_in[1];
    const float* Wk  = (const float*)d_in[2];
    const float* Wv  = (const float*)d_in[3];
    const float* Wo  = (const float*)d_in[4];
    const float* qnw = (const float*)d_in[5];
    const float* knw = (const float*)d_in[6];
    const float* cs  = (const float*)d_in[7];
    const float* sn  = (const float*)d_in[8];

    __half *qkvh, *xp, *ap, *wqkvt, *wot;
    __half *qhh, *khh;
    cudaGetSymbolAddress((void**)&qkvh, g_qkvh);
    cudaGetSymbolAddress((void**)&xp, g_xp);
    cudaGetSymbolAddress((void**)&ap, g_ap);
    cudaGetSymbolAddress((void**)&wqkvt, g_wqkvt);
    cudaGetSymbolAddress((void**)&wot, g_wot);
    cudaGetSymbolAddress((void**)&qhh, g_qh);
    cudaGetSymbolAddress((void**)&khh, g_kh);

    cudaFuncSetAttribute(gemm_mma, cudaFuncAttributeMaxDynamicSharedMemorySize, GEMM_SMEM);
    cudaFuncSetAttribute(flash_mma, cudaFuncAttributeMaxDynamicSharedMemorySize, FL_SMEM);

    // convert inputs + weights (QKV weights concatenated along N)
    conv_a<<<8192, 256>>>(x, xp);
    conv_w<<<dim3(64, 64), 256>>>(Wq, wqkvt, 2048);
    conv_w<<<dim3(32, 64), 256>>>(Wk, wqkvt + (size_t)2048 * KP, 1024);
    conv_w<<<dim3(32, 64), 256>>>(Wv, wqkvt + (size_t)3072 * KP, 1024);
    conv_w<<<dim3(64, 64), 256>>>(Wo, wot, 2048);

    // fused QKV projection (single-f16 HMMA), f16 output: [Q | K | V], [4096, 4096]
    gemm_mma<<<dim3(32, 32), 256, GEMM_SMEM>>>(xp, wqkvt, nullptr, qkvh, 4096);

    // fused RMSNorm + RoPE for Q and K in one launch
    const float qscale = (float)(0.08838834764831845 * 1.4426950408889634);
    norm_rope_split<<<12288, 256>>>(qkvh, qnw, knw, cs, sn, qhh, khh, qscale);

    // flash attention (single-f16; V read straight from the fused buffer; 2 CTAs/SM)
    flash_mma<<<dim3(16, Hh, Bsz), 256, FL_SMEM>>>(qhh, khh, qkvh, ap);

    // output projection (single-f16, fp32 output)
    gemm_mma<<<dim3(16, 32), 256, GEMM_SMEM>>>(ap, wot, (float*)d_out, nullptr, 2048);
}